// round 2
// baseline (speedup 1.0000x reference)
#include <cuda_runtime.h>
#include <cstdint>

// Problem shape (fixed by the reference)
#define S_LEN 2048
#define B_SZ  32
#define I_DIM 256
#define H_DIM 512

// ---------------- recurrence config ----------------
#define NCLUSTERS    16   // 16 clusters x 2 batches = 32 batches
#define CRANKS       8    // CTAs per cluster
#define ROWS_PER_CTA 64   // H_DIM / CRANKS
#define REC_THREADS  512

// th exchange buffer in global (L2-resident): [cluster][parity][batch-in-cluster][H]
__device__ float g_th[NCLUSTERS][2][2][H_DIM];

// ---------------- xproj GEMM: out[m,n] = sum_k x[m,k] * Wx[n,k] ----------------
#define BM 128
#define BN 128
#define BK 16

__global__ void __launch_bounds__(256, 2)
xproj_kernel(const float* __restrict__ x,
             const float* __restrict__ Wx,
             float* __restrict__ out)
{
    __shared__ float As[BK][BM];
    __shared__ float Bs[BK][BN];
    const int tid = threadIdx.x;
    const int m0 = blockIdx.y * BM;
    const int n0 = blockIdx.x * BN;
    const int tx = tid & 15;
    const int ty = tid >> 4;

    float acc[8][8];
#pragma unroll
    for (int i = 0; i < 8; i++)
#pragma unroll
        for (int j = 0; j < 8; j++) acc[i][j] = 0.f;

    const float* Aptr = x  + (size_t)m0 * I_DIM;
    const float* Bptr = Wx + (size_t)n0 * I_DIM;

    for (int k0 = 0; k0 < I_DIM; k0 += BK) {
#pragma unroll
        for (int l = 0; l < 2; l++) {
            int idx = tid + l * 256;        // 0..511
            int r   = idx >> 2;             // 0..127
            int c4  = (idx & 3) * 4;        // 0,4,8,12
            float4 a = *(const float4*)(Aptr + (size_t)r * I_DIM + k0 + c4);
            As[c4 + 0][r] = a.x; As[c4 + 1][r] = a.y;
            As[c4 + 2][r] = a.z; As[c4 + 3][r] = a.w;
            float4 b = *(const float4*)(Bptr + (size_t)r * I_DIM + k0 + c4);
            Bs[c4 + 0][r] = b.x; Bs[c4 + 1][r] = b.y;
            Bs[c4 + 2][r] = b.z; Bs[c4 + 3][r] = b.w;
        }
        __syncthreads();
#pragma unroll
        for (int kk = 0; kk < BK; kk++) {
            float ra[8], rb[8];
            float4 ra0 = *(const float4*)&As[kk][ty * 8];
            float4 ra1 = *(const float4*)&As[kk][ty * 8 + 4];
            ra[0]=ra0.x; ra[1]=ra0.y; ra[2]=ra0.z; ra[3]=ra0.w;
            ra[4]=ra1.x; ra[5]=ra1.y; ra[6]=ra1.z; ra[7]=ra1.w;
            float4 rb0 = *(const float4*)&Bs[kk][tx * 8];
            float4 rb1 = *(const float4*)&Bs[kk][tx * 8 + 4];
            rb[0]=rb0.x; rb[1]=rb0.y; rb[2]=rb0.z; rb[3]=rb0.w;
            rb[4]=rb1.x; rb[5]=rb1.y; rb[6]=rb1.z; rb[7]=rb1.w;
#pragma unroll
            for (int i = 0; i < 8; i++)
#pragma unroll
                for (int j = 0; j < 8; j++)
                    acc[i][j] += ra[i] * rb[j];
        }
        __syncthreads();
    }

#pragma unroll
    for (int i = 0; i < 8; i++) {
        float* o = out + (size_t)(m0 + ty * 8 + i) * H_DIM + n0 + tx * 8;
        *(float4*)o       = make_float4(acc[i][0], acc[i][1], acc[i][2], acc[i][3]);
        *(float4*)(o + 4) = make_float4(acc[i][4], acc[i][5], acc[i][6], acc[i][7]);
    }
}

// ---------------- recurrence ----------------
// grid = 128 CTAs as 16 clusters of 8. Cluster c handles batches (2c, 2c+1).
// CTA rank r owns H rows [r*64, r*64+64); its Wh slice lives in registers.
// Thread t: row-pair jp = t&31 (rows 2jp, 2jp+1), k-chunk kb = t>>5 (32 k's).
// Per step: GEMV partials -> smem reduce -> 128 threads update h + tanh ->
// write th to g_th[parity^1] -> one cluster barrier (release/acquire).
__global__ void __cluster_dims__(CRANKS, 1, 1) __launch_bounds__(REC_THREADS, 1)
rec_kernel(const float* __restrict__ Wh,
           const float* __restrict__ tau,
           const float* __restrict__ bias,
           float* __restrict__ out)    // holds xproj; overwritten in place with h
{
    const int cid  = blockIdx.x / CRANKS;
    const int rank = blockIdx.x % CRANKS;
    const int t    = threadIdx.x;
    const int jp   = t & 31;
    const int kb   = t >> 5;          // == warp id
    const int j0   = 2 * jp;
    const int j1   = j0 + 1;

    // Load this thread's Wh slice into registers (persistent for 2048 steps)
    float w0[32], w1[32];
    {
        const float* r0 = Wh + (size_t)(rank * ROWS_PER_CTA + j0) * H_DIM + kb * 32;
        const float* r1 = Wh + (size_t)(rank * ROWS_PER_CTA + j1) * H_DIM + kb * 32;
#pragma unroll
        for (int i = 0; i < 8; i++) {
            float4 a = *(const float4*)(r0 + i * 4);
            w0[i*4+0]=a.x; w0[i*4+1]=a.y; w0[i*4+2]=a.z; w0[i*4+3]=a.w;
            float4 b = *(const float4*)(r1 + i * 4);
            w1[i*4+0]=b.x; w1[i*4+1]=b.y; w1[i*4+2]=b.z; w1[i*4+3]=b.w;
        }
    }

    __shared__ float part[16][128];

    // Per-output state (threads t < 128 each own one (batch, row) output)
    const int bb = t >> 6;            // batch within cluster (0/1)
    const int j  = t & 63;            // local row
    const int hg = rank * ROWS_PER_CTA + j;
    const int b  = cid * 2 + bb;
    float* outp = out + (size_t)b * S_LEN * H_DIM + hg;

    float h = 0.f, tau_r = 1.f, bias_r = 0.f;
    if (t < 128) {
        tau_r  = tau[hg];
        bias_r = bias[hg];
        // re-init th(step 0) = tanh(0) = 0 EVERY launch (graph replays!)
        g_th[cid][0][bb][hg] = 0.f;
    }
    asm volatile("barrier.cluster.arrive.aligned;\n\t"
                 "barrier.cluster.wait.aligned;" ::: "memory");

    for (int step = 0; step < S_LEN; step++) {
        const int p = step & 1;

        // prefetch this step's input projection (hidden behind GEMV)
        float xp = 0.f;
        if (t < 128) xp = outp[(size_t)step * H_DIM];

        // GEMV partials over this thread's 32-k chunk, 2 rows x 2 batches
        const float4* t0 = (const float4*)&g_th[cid][p][0][kb * 32];
        const float4* t1 = (const float4*)&g_th[cid][p][1][kb * 32];
        float a00 = 0.f, a01 = 0.f, a10 = 0.f, a11 = 0.f;
#pragma unroll
        for (int i = 0; i < 8; i++) {
            float4 u = t0[i];
            float4 v = t1[i];
            a00 += w0[i*4+0]*u.x; a00 += w0[i*4+1]*u.y; a00 += w0[i*4+2]*u.z; a00 += w0[i*4+3]*u.w;
            a01 += w1[i*4+0]*u.x; a01 += w1[i*4+1]*u.y; a01 += w1[i*4+2]*u.z; a01 += w1[i*4+3]*u.w;
            a10 += w0[i*4+0]*v.x; a10 += w0[i*4+1]*v.y; a10 += w0[i*4+2]*v.z; a10 += w0[i*4+3]*v.w;
            a11 += w1[i*4+0]*v.x; a11 += w1[i*4+1]*v.y; a11 += w1[i*4+2]*v.z; a11 += w1[i*4+3]*v.w;
        }
        // part[kb][jp*4 + {0: (b0,j0), 1: (b0,j1), 2: (b1,j0), 3: (b1,j1)}]
        *(float4*)&part[kb][jp * 4] = make_float4(a00, a01, a10, a11);
        __syncthreads();

        if (t < 128) {
            const int idx = (j >> 1) * 4 + bb * 2 + (j & 1);
            float v = 0.f;
#pragma unroll
            for (int w = 0; w < 16; w++) v += part[w][idx];

            // h_{t+1} = h + (-h + xp + v + bias) / tau    (DT = 1)
            h = h + (xp - h + v + bias_r) / tau_r;
            outp[(size_t)step * H_DIM] = h;           // overwrite xproj in place
            g_th[cid][p ^ 1][bb][hg] = tanhf(h);      // th for next step
        }
        // One cluster barrier per step: release th writes, acquire before next
        // step's reads; double-buffered g_th makes a single barrier sufficient.
        // (Also guards smem `part` reuse: next-step STS happens only after all
        // readers passed the barrier.)
        asm volatile("barrier.cluster.arrive.aligned;\n\t"
                     "barrier.cluster.wait.aligned;" ::: "memory");
    }
}

extern "C" void kernel_launch(void* const* d_in, const int* in_sizes, int n_in,
                              void* d_out, int out_size)
{
    const float* x    = (const float*)d_in[0];
    const float* Wx   = (const float*)d_in[1];
    const float* Wh   = (const float*)d_in[2];
    const float* tau  = (const float*)d_in[3];
    const float* bias = (const float*)d_in[4];
    float* out = (float*)d_out;

    dim3 g1(H_DIM / BN, (B_SZ * S_LEN) / BM);   // (4, 512)
    xproj_kernel<<<g1, 256>>>(x, Wx, out);

    rec_kernel<<<NCLUSTERS * CRANKS, REC_THREADS>>>(Wh, tau, bias, out);
}

// round 3
// speedup vs baseline: 1.7041x; 1.7041x over previous
#include <cuda_runtime.h>
#include <cstdint>

#define S_LEN 2048
#define B_SZ  32
#define I_DIM 256
#define H_DIM 512

#define NCLUSTERS    16
#define CRANKS       8
#define ROWS_PER_CTA 64
#define REC_THREADS  512

// ---------------- PTX helpers ----------------
__device__ __forceinline__ uint32_t smem_u32(const void* p) {
    uint32_t a;
    asm("{ .reg .u64 t; cvta.to.shared.u64 t, %1; cvt.u32.u64 %0, t; }" : "=r"(a) : "l"(p));
    return a;
}
__device__ __forceinline__ uint32_t mapa_cluster(uint32_t addr, uint32_t rank) {
    uint32_t r;
    asm("mapa.shared::cluster.u32 %0, %1, %2;" : "=r"(r) : "r"(addr), "r"(rank));
    return r;
}
__device__ __forceinline__ void mbar_init(uint32_t mbar, uint32_t cnt) {
    asm volatile("mbarrier.init.shared.b64 [%0], %1;" :: "r"(mbar), "r"(cnt) : "memory");
}
__device__ __forceinline__ void mbar_expect_tx(uint32_t mbar, uint32_t bytes) {
    asm volatile("mbarrier.arrive.expect_tx.shared.b64 _, [%0], %1;" :: "r"(mbar), "r"(bytes) : "memory");
}
__device__ __forceinline__ void mbar_wait(uint32_t mbar, uint32_t phase) {
    uint32_t done = 0;
    while (!done) {
        asm volatile(
            "{\n\t.reg .pred p;\n\t"
            "mbarrier.try_wait.parity.acquire.cluster.shared::cta.b64 p, [%1], %2, 0x989680;\n\t"
            "selp.b32 %0, 1, 0, p;\n\t}"
            : "=r"(done) : "r"(mbar), "r"(phase) : "memory");
    }
}
__device__ __forceinline__ void st_async_f32(uint32_t daddr, float v, uint32_t mbar) {
    asm volatile("st.async.shared::cluster.mbarrier::complete_tx::bytes.b32 [%0], %1, [%2];"
                 :: "r"(daddr), "r"(__float_as_uint(v)), "r"(mbar) : "memory");
}
__device__ __forceinline__ unsigned long long ffma2(unsigned long long a, unsigned long long b,
                                                    unsigned long long c) {
    unsigned long long d;
    asm("fma.rn.f32x2 %0, %1, %2, %3;" : "=l"(d) : "l"(a), "l"(b), "l"(c));
    return d;
}
__device__ __forceinline__ float fold2(unsigned long long v) {
    union { unsigned long long u; float2 f; } c; c.u = v;
    return c.f.x + c.f.y;
}
__device__ __forceinline__ float fast_tanh(float h) {
    float hc = fminf(fmaxf(h, -15.f), 15.f);
    float e2 = __expf(2.f * hc);
    return __fdividef(e2 - 1.f, e2 + 1.f);
}
__device__ __forceinline__ void cluster_sync() {
    asm volatile("barrier.cluster.arrive.aligned;\n\tbarrier.cluster.wait.aligned;" ::: "memory");
}

// ---------------- xproj GEMM: out[m,n] = sum_k x[m,k] * Wx[n,k] ----------------
#define BM 128
#define BN 128
#define BK 16

__global__ void __launch_bounds__(256, 2)
xproj_kernel(const float* __restrict__ x,
             const float* __restrict__ Wx,
             float* __restrict__ out)
{
    __shared__ float As[BK][BM];
    __shared__ float Bs[BK][BN];
    const int tid = threadIdx.x;
    const int m0 = blockIdx.y * BM;
    const int n0 = blockIdx.x * BN;
    const int tx = tid & 15;
    const int ty = tid >> 4;

    float acc[8][8];
#pragma unroll
    for (int i = 0; i < 8; i++)
#pragma unroll
        for (int j = 0; j < 8; j++) acc[i][j] = 0.f;

    const float* Aptr = x  + (size_t)m0 * I_DIM;
    const float* Bptr = Wx + (size_t)n0 * I_DIM;

    for (int k0 = 0; k0 < I_DIM; k0 += BK) {
#pragma unroll
        for (int l = 0; l < 2; l++) {
            int idx = tid + l * 256;
            int r   = idx >> 2;
            int c4  = (idx & 3) * 4;
            float4 a = *(const float4*)(Aptr + (size_t)r * I_DIM + k0 + c4);
            As[c4 + 0][r] = a.x; As[c4 + 1][r] = a.y;
            As[c4 + 2][r] = a.z; As[c4 + 3][r] = a.w;
            float4 b = *(const float4*)(Bptr + (size_t)r * I_DIM + k0 + c4);
            Bs[c4 + 0][r] = b.x; Bs[c4 + 1][r] = b.y;
            Bs[c4 + 2][r] = b.z; Bs[c4 + 3][r] = b.w;
        }
        __syncthreads();
#pragma unroll
        for (int kk = 0; kk < BK; kk++) {
            float ra[8], rb[8];
            float4 ra0 = *(const float4*)&As[kk][ty * 8];
            float4 ra1 = *(const float4*)&As[kk][ty * 8 + 4];
            ra[0]=ra0.x; ra[1]=ra0.y; ra[2]=ra0.z; ra[3]=ra0.w;
            ra[4]=ra1.x; ra[5]=ra1.y; ra[6]=ra1.z; ra[7]=ra1.w;
            float4 rb0 = *(const float4*)&Bs[kk][tx * 8];
            float4 rb1 = *(const float4*)&Bs[kk][tx * 8 + 4];
            rb[0]=rb0.x; rb[1]=rb0.y; rb[2]=rb0.z; rb[3]=rb0.w;
            rb[4]=rb1.x; rb[5]=rb1.y; rb[6]=rb1.z; rb[7]=rb1.w;
#pragma unroll
            for (int i = 0; i < 8; i++)
#pragma unroll
                for (int j = 0; j < 8; j++)
                    acc[i][j] += ra[i] * rb[j];
        }
        __syncthreads();
    }

#pragma unroll
    for (int i = 0; i < 8; i++) {
        float* o = out + (size_t)(m0 + ty * 8 + i) * H_DIM + n0 + tx * 8;
        *(float4*)o       = make_float4(acc[i][0], acc[i][1], acc[i][2], acc[i][3]);
        *(float4*)(o + 4) = make_float4(acc[i][4], acc[i][5], acc[i][6], acc[i][7]);
    }
}

// ---------------- recurrence ----------------
// 16 clusters x 8 CTAs. Cluster c: batches (2c, 2c+1). CTA rank r: H rows
// [r*64, r*64+64), Wh slice in registers as f32x2 pairs. th exchanged via
// st.async DSMEM push into every cluster CTA's smem, double-buffered,
// mbarrier complete_tx. One try_wait per step; no cluster.sync in the loop.
struct RecSmem {
    float th[2][2][H_DIM];     // [buf][batch][row]  8KB
    float part[16][128];       // 8KB
    unsigned long long mbar[2];
};

__global__ void __cluster_dims__(CRANKS, 1, 1) __launch_bounds__(REC_THREADS, 1)
rec_kernel(const float* __restrict__ Wh,
           const float* __restrict__ tau,
           const float* __restrict__ bias,
           float* __restrict__ out)
{
    __shared__ __align__(16) RecSmem sm;

    const int cid  = blockIdx.x / CRANKS;
    const int rank = blockIdx.x % CRANKS;
    const int t    = threadIdx.x;
    const int jp   = t & 31;
    const int kb   = t >> 5;
    const int j0   = 2 * jp;

    // Wh slice: rows j0, j0+1; k in [kb*32, kb*32+32), packed as f32x2 pairs
    unsigned long long wp0[16], wp1[16];
    {
        const ulonglong2* r0 = (const ulonglong2*)(Wh + (size_t)(rank * ROWS_PER_CTA + j0)     * H_DIM + kb * 32);
        const ulonglong2* r1 = (const ulonglong2*)(Wh + (size_t)(rank * ROWS_PER_CTA + j0 + 1) * H_DIM + kb * 32);
#pragma unroll
        for (int i = 0; i < 8; i++) {
            ulonglong2 a = r0[i]; wp0[2*i] = a.x; wp0[2*i+1] = a.y;
            ulonglong2 b = r1[i]; wp1[2*i] = b.x; wp1[2*i+1] = b.y;
        }
    }

    const uint32_t th_base   = smem_u32(&sm.th[0][0][0]);
    const uint32_t mbar_base = smem_u32(&sm.mbar[0]);
    const uint32_t mbar_rel  = mbar_base - th_base;

    uint32_t peer_th[CRANKS];
#pragma unroll
    for (int r = 0; r < CRANKS; r++) peer_th[r] = mapa_cluster(th_base, r);

    if (t == 0) {
        mbar_init(mbar_base,     1);
        mbar_init(mbar_base + 8, 1);
        mbar_expect_tx(mbar_base,     4096);   // buf0, first used at step 2
        mbar_expect_tx(mbar_base + 8, 4096);   // buf1, first used at step 1
    }
    __syncthreads();
    cluster_sync();   // all peers' mbars live before any st.async

    // per-output state
    const int bb = t >> 6;
    const int j  = t & 63;
    const int hg = rank * ROWS_PER_CTA + j;
    const int b  = cid * 2 + bb;
    float* outp = out + (size_t)b * S_LEN * H_DIM + hg;

    float h = 0.f, inv_tau = 1.f, bias_r = 0.f;
    int ridx = 0;
    if (t < 128) {
        inv_tau = 1.0f / tau[hg];
        bias_r  = bias[hg];
        ridx = (j >> 1) * 4 + bb * 2 + (j & 1);
    }

    // send helper offsets
    const uint32_t send_off_b = (uint32_t)(bb * H_DIM + hg) * 4u;  // add buf*2*H*4

    // ---- step 0: h0 = 0, th(0) = 0 -> v = 0 ----
    if (t < 128) {
        float xp = outp[0];
        h = (xp + bias_r) * inv_tau;
        outp[0] = h;
        float thv = fast_tanh(h);
        uint32_t doff = (uint32_t)(2 * H_DIM * 4) + send_off_b;    // buf 1
#pragma unroll
        for (int r = 0; r < CRANKS; r++)
            st_async_f32(peer_th[r] + doff, thv, peer_th[r] + mbar_rel + 8);
    }

    uint32_t ph0 = 0, ph1 = 0;

    // ---- one step body: read rbuf, write wbuf = rbuf^1 ----
#define STEP_BODY(STEP, RBUF, MB_OFF, PH)                                          \
    {                                                                              \
        float xp = 0.f;                                                            \
        if (t < 128) xp = outp[(size_t)(STEP) * H_DIM];                            \
        mbar_wait(mbar_base + (MB_OFF), (PH));                                     \
        if (t == 0) mbar_expect_tx(mbar_base + (MB_OFF), 4096);                    \
        const ulonglong2* t0 = (const ulonglong2*)&sm.th[(RBUF)][0][kb * 32];      \
        const ulonglong2* t1 = (const ulonglong2*)&sm.th[(RBUF)][1][kb * 32];      \
        unsigned long long a00 = 0ull, a01 = 0ull, a10 = 0ull, a11 = 0ull;         \
        _Pragma("unroll")                                                          \
        for (int i = 0; i < 8; i++) {                                              \
            ulonglong2 U = t0[i];                                                  \
            ulonglong2 V = t1[i];                                                  \
            a00 = ffma2(wp0[2*i],   U.x, a00);                                     \
            a00 = ffma2(wp0[2*i+1], U.y, a00);                                     \
            a01 = ffma2(wp1[2*i],   U.x, a01);                                     \
            a01 = ffma2(wp1[2*i+1], U.y, a01);                                     \
            a10 = ffma2(wp0[2*i],   V.x, a10);                                     \
            a10 = ffma2(wp0[2*i+1], V.y, a10);                                     \
            a11 = ffma2(wp1[2*i],   V.x, a11);                                     \
            a11 = ffma2(wp1[2*i+1], V.y, a11);                                     \
        }                                                                          \
        *(float4*)&sm.part[kb][jp * 4] =                                           \
            make_float4(fold2(a00), fold2(a01), fold2(a10), fold2(a11));           \
        __syncthreads();                                                           \
        if (t < 128) {                                                             \
            float v = 0.f;                                                         \
            _Pragma("unroll")                                                      \
            for (int w = 0; w < 16; w++) v += sm.part[w][ridx];                    \
            h = h + (xp - h + v + bias_r) * inv_tau;                               \
            outp[(size_t)(STEP) * H_DIM] = h;                                      \
            float thv = fast_tanh(h);                                              \
            uint32_t doff = (uint32_t)(((RBUF) ^ 1) * 2 * H_DIM * 4) + send_off_b; \
            uint32_t moff = mbar_rel + (((RBUF) ^ 1) * 8);                         \
            _Pragma("unroll")                                                      \
            for (int r = 0; r < CRANKS; r++)                                       \
                st_async_f32(peer_th[r] + doff, thv, peer_th[r] + moff);           \
        }                                                                          \
    }

    // steps 1..2046 in pairs (odd reads buf1, even reads buf0), then 2047
    for (int s = 1; s < S_LEN - 1; s += 2) {
        STEP_BODY(s,     1, 8, ph1); ph1 ^= 1;
        STEP_BODY(s + 1, 0, 0, ph0); ph0 ^= 1;
    }
    STEP_BODY(S_LEN - 1, 1, 8, ph1); ph1 ^= 1;
#undef STEP_BODY

    cluster_sync();   // don't exit while peers' st.async may target our smem
}

extern "C" void kernel_launch(void* const* d_in, const int* in_sizes, int n_in,
                              void* d_out, int out_size)
{
    const float* x    = (const float*)d_in[0];
    const float* Wx   = (const float*)d_in[1];
    const float* Wh   = (const float*)d_in[2];
    const float* tau  = (const float*)d_in[3];
    const float* bias = (const float*)d_in[4];
    float* out = (float*)d_out;

    dim3 g1(H_DIM / BN, (B_SZ * S_LEN) / BM);
    xproj_kernel<<<g1, 256>>>(x, Wx, out);

    rec_kernel<<<NCLUSTERS * CRANKS, REC_THREADS>>>(Wh, tau, bias, out);
}